// round 13
// baseline (speedup 1.0000x reference)
#include <cuda_runtime.h>

#define N_NODES 160000
#define NODES_PER_GRAPH 20000
#define NBATCH 8
#define N_EDGES 5120000
#define HID 16
#define TKILE 1024

// ---------------- device scratch (no allocation allowed) ----------------
__device__ float d_s1[N_NODES];            // layer-1 scalar aggregation (zero invariant)
__device__ float d_p[N_NODES];             // h . Wr2 per node
__device__ float d_gt[N_NODES];            // h2 transposed: [20000][8]
__device__ float d_part[16 * 4000 * 8];    // K-split partials (16 splits max)
__device__ float d_y1[4000 * NBATCH];
__device__ float d_y2[800 * NBATCH];
__device__ float d_y3[160 * NBATCH];

// ---------------- graph kernels ----------------

// pass 1: s1[tgt] += ew * x[src]   (8 edges per thread)
__global__ void edge_pass1(const int* __restrict__ src, const int* __restrict__ tgt,
                           const float* __restrict__ ew, const float* __restrict__ x) {
    int i = blockIdx.x * blockDim.x + threadIdx.x;
    int base = i * 8;
    if (base >= N_EDGES) return;
    int4   s0 = *(const int4*)(src + base);
    int4   s1v = *(const int4*)(src + base + 4);
    int4   t0 = *(const int4*)(tgt + base);
    int4   t1 = *(const int4*)(tgt + base + 4);
    float4 w0 = *(const float4*)(ew + base);
    float4 w1 = *(const float4*)(ew + base + 4);
    atomicAdd(&d_s1[t0.x], w0.x * __ldg(&x[s0.x]));
    atomicAdd(&d_s1[t0.y], w0.y * __ldg(&x[s0.y]));
    atomicAdd(&d_s1[t0.z], w0.z * __ldg(&x[s0.z]));
    atomicAdd(&d_s1[t0.w], w0.w * __ldg(&x[s0.w]));
    atomicAdd(&d_s1[t1.x], w1.x * __ldg(&x[s1v.x]));
    atomicAdd(&d_s1[t1.y], w1.y * __ldg(&x[s1v.y]));
    atomicAdd(&d_s1[t1.z], w1.z * __ldg(&x[s1v.z]));
    atomicAdd(&d_s1[t1.w], w1.w * __ldg(&x[s1v.w]));
}

__global__ void node_kernel(const float* __restrict__ x,
                            const float* __restrict__ Wr1, const float* __restrict__ br1,
                            const float* __restrict__ Ws1, const float* __restrict__ Wr2,
                            const float* __restrict__ br2, const float* __restrict__ Ws2) {
    int n = blockIdx.x * blockDim.x + threadIdx.x;
    if (n >= N_NODES) return;
    float s  = d_s1[n];
    d_s1[n] = 0.f;   // keep "s1 == 0 at entry" invariant across graph replays
    float xv = x[n];
    float pa = 0.f, qa = 0.f;
#pragma unroll
    for (int f = 0; f < HID; f++) {
        float h = fmaf(s, __ldg(&Wr1[f]), fmaf(xv, __ldg(&Ws1[f]), __ldg(&br1[f])));
        h = fmaxf(h, 0.f);
        pa = fmaf(__ldg(&Wr2[f]), h, pa);
        qa = fmaf(__ldg(&Ws2[f]), h, qa);
    }
    d_p[n] = pa;
    unsigned nu = (unsigned)n;
    unsigned b  = nu / NODES_PER_GRAPH;
    unsigned k  = nu - b * NODES_PER_GRAPH;
    d_gt[k * NBATCH + b] = qa + __ldg(&br2[0]);
}

// pass 2: gt[transposed(tgt)] += ew * p[src]   (8 edges per thread)
__global__ void edge_pass2(const int* __restrict__ src, const int* __restrict__ tgt,
                           const float* __restrict__ ew) {
    int i = blockIdx.x * blockDim.x + threadIdx.x;
    int base = i * 8;
    if (base >= N_EDGES) return;
    int4   s0 = *(const int4*)(src + base);
    int4   s1v = *(const int4*)(src + base + 4);
    int4   t0 = *(const int4*)(tgt + base);
    int4   t1 = *(const int4*)(tgt + base + 4);
    float4 w0 = *(const float4*)(ew + base);
    float4 w1 = *(const float4*)(ew + base + 4);
#define EP2_ONE(SS, TT, WW)                                            \
    {                                                                  \
        unsigned tu = (unsigned)(TT);                                  \
        unsigned b  = tu / NODES_PER_GRAPH;                            \
        unsigned k  = tu - b * NODES_PER_GRAPH;                        \
        atomicAdd(&d_gt[k * NBATCH + b], (WW) * __ldg(&d_p[SS]));      \
    }
    EP2_ONE(s0.x, t0.x, w0.x);
    EP2_ONE(s0.y, t0.y, w0.y);
    EP2_ONE(s0.z, t0.z, w0.z);
    EP2_ONE(s0.w, t0.w, w0.w);
    EP2_ONE(s1v.x, t1.x, w1.x);
    EP2_ONE(s1v.y, t1.y, w1.y);
    EP2_ONE(s1v.z, t1.z, w1.z);
    EP2_ONE(s1v.w, t1.w, w1.w);
#undef EP2_ONE
}

// ---------------- packed f32x2 helpers ----------------
__device__ __forceinline__ unsigned long long pack2(float v) {
    unsigned long long r;
    unsigned u = __float_as_uint(v);
    asm("mov.b64 %0, {%1, %1};" : "=l"(r) : "r"(u));
    return r;
}
__device__ __forceinline__ unsigned long long fma2(unsigned long long a,
                                                   unsigned long long b,
                                                   unsigned long long c) {
    unsigned long long d;
    asm("fma.rn.f32x2 %0, %1, %2, %3;" : "=l"(d) : "l"(a), "l"(b), "l"(c));
    return d;
}
__device__ __forceinline__ unsigned long long add2(unsigned long long a,
                                                   unsigned long long b) {
    unsigned long long d;
    asm("add.rn.f32x2 %0, %1, %2;" : "=l"(d) : "l"(a), "l"(b));
    return d;
}

// ---- gemm40: 40 rows/block (8 warps x 5 rows), K-split, packed f32x2,
//      LDG.128 W loads + swizzled-smem LDS.128 g loads, prefetch-1 W pipeline.
// g smem layout: 16B entry (c, pq, L) holds plane p's float2 for
//   k = 128c + 4L + 2q and k+1, where pq = 2p+q. LDS.128 at lanes L=0..31 is a
//   16B-stride access -> 512B contiguous -> 4 wavefronts, conflict-free.
// REQUIREMENT: KS % 4 == 0 (k0 must be 16B-aligned for LDG.128 on W).
// part[ks*J*8 + j*8 + b] = sum_{k in split ks} W[j,k] * gin_t[k][b]
#define ROWS_W 5
#define NCHUNK (TKILE / 128)
__global__ void __launch_bounds__(256, 2)
gemm40(const float* __restrict__ W, int gin_sel, int Ktot, int KS, int nsplit, int J) {
    const float* __restrict__ gin = (gin_sel == 0) ? d_gt : d_y1;

    __shared__ uint4 gs4[NCHUNK * 8 * 32];   // 32 KB: [chunk][pq][lane]

    int tid  = threadIdx.x;
    int lane = tid & 31;
    int wid  = tid >> 5;
    int rg   = blockIdx.x / nsplit;
    int ks   = blockIdx.x - rg * nsplit;
    int j0   = rg * (8 * ROWS_W);
    int row0 = j0 + wid * ROWS_W;
    int k0   = ks * KS;
    int kend = min(k0 + KS, Ktot);

    unsigned long long acc[ROWS_W][4];
#pragma unroll
    for (int r = 0; r < ROWS_W; r++)
#pragma unroll
        for (int p = 0; p < 4; p++) acc[r][p] = 0ull;

    for (int kt = k0; kt < kend; kt += TKILE) {
        int kv = min(TKILE, kend - kt);
        __syncthreads();
        // stage g tile into swizzled layout, zero-pad beyond kv
        {
            unsigned long long* gs8 = (unsigned long long*)gs4;  // 8B units
            for (int k = tid; k < TKILE; k += 256) {
                float4 a, b;
                if (k < kv) {
                    a = __ldg((const float4*)(gin + (size_t)(kt + k) * 8));
                    b = __ldg((const float4*)(gin + (size_t)(kt + k) * 8 + 4));
                } else {
                    a = make_float4(0.f, 0.f, 0.f, 0.f);
                    b = a;
                }
                int c  = k >> 7;
                int kk = k & 127;
                int L  = kk >> 2;
                int q  = (kk >> 1) & 1;
                int rr = kk & 1;
                int base8 = ((c << 3) + q) * 64 + L * 2 + rr;
                float2 p0 = make_float2(a.x, a.y);
                float2 p1 = make_float2(a.z, a.w);
                float2 p2 = make_float2(b.x, b.y);
                float2 p3 = make_float2(b.z, b.w);
                gs8[base8 + 0 * 128] = *(unsigned long long*)&p0;
                gs8[base8 + 1 * 128] = *(unsigned long long*)&p1;
                gs8[base8 + 2 * 128] = *(unsigned long long*)&p2;
                gs8[base8 + 3 * 128] = *(unsigned long long*)&p3;
            }
        }
        __syncthreads();

        const float* Wr[ROWS_W];
#pragma unroll
        for (int r = 0; r < ROWS_W; r++) Wr[r] = W + (size_t)(row0 + r) * Ktot + kt;

        int iters = kv >> 7;          // full 128-k chunks
        int rem   = kv - (iters << 7);

        if (iters > 0) {
            // prefetch chunk 0: this lane's 4 consecutive k per row (LDG.128)
            float4 wc[ROWS_W];
#pragma unroll
            for (int r = 0; r < ROWS_W; r++)
                wc[r] = __ldg((const float4*)(Wr[r] + 4 * lane));

            for (int it = 0; it < iters; it++) {
                // prefetch next chunk's W (guarded; unused value if last)
                float4 wn[ROWS_W];
                bool have_next = (it + 1 < iters);
#pragma unroll
                for (int r = 0; r < ROWS_W; r++)
                    wn[r] = have_next
                          ? __ldg((const float4*)(Wr[r] + ((it + 1) << 7) + 4 * lane))
                          : make_float4(0.f, 0.f, 0.f, 0.f);

                const uint4* gsc = gs4 + (it << 8);  // this chunk: 8*32 entries

                // q = 0: k-pair (4L, 4L+1)
                {
                    uint4 v[4];
#pragma unroll
                    for (int p = 0; p < 4; p++)
                        v[p] = gsc[(p * 2 + 0) * 32 + lane];
#pragma unroll
                    for (int r = 0; r < ROWS_W; r++) {
                        unsigned long long w0 = pack2(wc[r].x);
                        unsigned long long w1 = pack2(wc[r].y);
#pragma unroll
                        for (int p = 0; p < 4; p++) {
                            unsigned long long g0 = *(unsigned long long*)&v[p].x;
                            unsigned long long g1 = *(unsigned long long*)&v[p].z;
                            acc[r][p] = fma2(w0, g0, acc[r][p]);
                            acc[r][p] = fma2(w1, g1, acc[r][p]);
                        }
                    }
                }
                // q = 1: k-pair (4L+2, 4L+3)
                {
                    uint4 v[4];
#pragma unroll
                    for (int p = 0; p < 4; p++)
                        v[p] = gsc[(p * 2 + 1) * 32 + lane];
#pragma unroll
                    for (int r = 0; r < ROWS_W; r++) {
                        unsigned long long w2 = pack2(wc[r].z);
                        unsigned long long w3 = pack2(wc[r].w);
#pragma unroll
                        for (int p = 0; p < 4; p++) {
                            unsigned long long g0 = *(unsigned long long*)&v[p].x;
                            unsigned long long g1 = *(unsigned long long*)&v[p].z;
                            acc[r][p] = fma2(w2, g0, acc[r][p]);
                            acc[r][p] = fma2(w3, g1, acc[r][p]);
                        }
                    }
                }
#pragma unroll
                for (int r = 0; r < ROWS_W; r++) wc[r] = wn[r];
            }
        }

        // epilogue: ragged remainder (guarded scalar loads; g smem zero-padded)
        if (rem > 0) {
            unsigned long long* gs8 = (unsigned long long*)gs4;
            int kb = iters << 7;
#pragma unroll
            for (int j = 0; j < 4; j++) {
                int kk = kb + 32 * j + lane;
                if (kk < kv) {
                    float wv[ROWS_W];
#pragma unroll
                    for (int r = 0; r < ROWS_W; r++) wv[r] = __ldg(Wr[r] + kk);
                    int c  = kk >> 7;
                    int kl = kk & 127;
                    int L  = kl >> 2;
                    int q  = (kl >> 1) & 1;
                    int rr = kl & 1;
                    int base8 = ((c << 3) + q) * 64 + L * 2 + rr;
#pragma unroll
                    for (int r = 0; r < ROWS_W; r++) {
                        unsigned long long wp = pack2(wv[r]);
#pragma unroll
                        for (int p = 0; p < 4; p++)
                            acc[r][p] = fma2(wp, gs8[base8 + p * 128], acc[r][p]);
                    }
                }
            }
        }
    }

    // cross-lane reduction; lanes 0..19 own one (row, b-pair) and store as u64
    unsigned long long keep = 0ull;
#pragma unroll
    for (int r = 0; r < ROWS_W; r++)
#pragma unroll
        for (int p = 0; p < 4; p++) {
            unsigned long long v = acc[r][p];
#pragma unroll
            for (int o = 16; o > 0; o >>= 1)
                v = add2(v, __shfl_xor_sync(0xffffffffu, v, o));
            if (lane == r * 4 + p) keep = v;
        }
    if (lane < ROWS_W * 4) {
        int r = lane >> 2;
        int p = lane & 3;
        *(unsigned long long*)&d_part[((size_t)ks * J + (row0 + r)) * 8 + 2 * p] = keep;
    }
}

// combine K-split partials: out[j][b] = relu(sum_s part[s][j][b] + bias[j])
__global__ void combine_kernel(const float* __restrict__ bias, int nsplit, int J,
                               int out_sel) {
    float* __restrict__ gout = (out_sel == 0) ? d_y1 : d_y2;
    int i = blockIdx.x * blockDim.x + threadIdx.x;
    if (i >= J * 8) return;
    int j = i >> 3;
    float v = __ldg(&bias[j]);
    for (int s = 0; s < nsplit; s++) v += d_part[(size_t)s * J * 8 + i];
    gout[i] = fmaxf(v, 0.f);
}

// batch-8 GEMV for layer 3 (160 x 800, tiny)
__global__ void gemm8v(const float* __restrict__ W, const float* __restrict__ bias,
                       int K, int do_relu) {
    const float* __restrict__ gin  = d_y2;
    float* __restrict__       gout = d_y3;

    __shared__ float red[64][8];
    int j0 = blockIdx.x * 8;
    int K4 = K >> 2;

    float acc[8][8];
#pragma unroll
    for (int j = 0; j < 8; j++)
#pragma unroll
        for (int b = 0; b < 8; b++) acc[j][b] = 0.f;

    const float4* gv = (const float4*)gin;
    for (int k4 = threadIdx.x; k4 < K4; k4 += 256) {
        float4 w[8];
#pragma unroll
        for (int j = 0; j < 8; j++)
            w[j] = __ldg((const float4*)(W + (size_t)(j0 + j) * K) + k4);
        float4 g[8];
#pragma unroll
        for (int i = 0; i < 8; i++) g[i] = __ldg(gv + (size_t)k4 * 8 + i);
#pragma unroll
        for (int j = 0; j < 8; j++) {
            float wj[4] = {w[j].x, w[j].y, w[j].z, w[j].w};
#pragma unroll
            for (int kk = 0; kk < 4; kk++) {
                float4 ga = g[kk * 2 + 0];
                float4 gb = g[kk * 2 + 1];
                acc[j][0] = fmaf(wj[kk], ga.x, acc[j][0]);
                acc[j][1] = fmaf(wj[kk], ga.y, acc[j][1]);
                acc[j][2] = fmaf(wj[kk], ga.z, acc[j][2]);
                acc[j][3] = fmaf(wj[kk], ga.w, acc[j][3]);
                acc[j][4] = fmaf(wj[kk], gb.x, acc[j][4]);
                acc[j][5] = fmaf(wj[kk], gb.y, acc[j][5]);
                acc[j][6] = fmaf(wj[kk], gb.z, acc[j][6]);
                acc[j][7] = fmaf(wj[kk], gb.w, acc[j][7]);
            }
        }
    }

    int lane = threadIdx.x & 31;
    int wid  = threadIdx.x >> 5;
#pragma unroll
    for (int j = 0; j < 8; j++) {
#pragma unroll
        for (int b = 0; b < 8; b++) {
            float v = acc[j][b];
#pragma unroll
            for (int o = 16; o > 0; o >>= 1)
                v += __shfl_down_sync(0xffffffffu, v, o);
            if (lane == 0) red[j * 8 + b][wid] = v;
        }
    }
    __syncthreads();
    if (threadIdx.x < 64) {
        int j = threadIdx.x >> 3;
        int b = threadIdx.x & 7;
        float v = 0.f;
#pragma unroll
        for (int w = 0; w < 8; w++) v += red[threadIdx.x][w];
        v += __ldg(&bias[j0 + j]);
        if (do_relu) v = fmaxf(v, 0.f);
        gout[(j0 + j) * 8 + b] = v;
    }
}

// final layer [8,160] @ W4^T [160,10] + b4, then log_softmax per row.
__global__ void final_kernel(const float* __restrict__ W4, const float* __restrict__ b4,
                             float* __restrict__ out) {
    int b    = threadIdx.x >> 5;
    int lane = threadIdx.x & 31;
    float z = -1e30f;
    if (lane < 10) {
        float acc = __ldg(&b4[lane]);
#pragma unroll 8
        for (int k = 0; k < 160; k++)
            acc = fmaf(__ldg(&W4[lane * 160 + k]), d_y3[k * 8 + b], acc);
        z = acc;
    }
    float m = z;
#pragma unroll
    for (int o = 16; o > 0; o >>= 1)
        m = fmaxf(m, __shfl_xor_sync(0xffffffffu, m, o));
    float e = (lane < 10) ? __expf(z - m) : 0.f;
    float ssum = e;
#pragma unroll
    for (int o = 16; o > 0; o >>= 1)
        ssum += __shfl_xor_sync(0xffffffffu, ssum, o);
    if (lane < 10) out[b * 10 + lane] = z - m - __logf(ssum);
}

// ---------------- launch ----------------
extern "C" void kernel_launch(void* const* d_in, const int* in_sizes, int n_in,
                              void* d_out, int out_size) {
    const float* x   = (const float*)d_in[0];
    const float* ew  = (const float*)d_in[1];
    const float* Wr1 = (const float*)d_in[2];
    const float* br1 = (const float*)d_in[3];
    const float* Ws1 = (const float*)d_in[4];
    const float* Wr2 = (const float*)d_in[5];
    const float* br2 = (const float*)d_in[6];
    const float* Ws2 = (const float*)d_in[7];
    const float* W1  = (const float*)d_in[8];
    const float* b1  = (const float*)d_in[9];
    const float* W2  = (const float*)d_in[10];
    const float* b2  = (const float*)d_in[11];
    const float* W3  = (const float*)d_in[12];
    const float* b3  = (const float*)d_in[13];
    const float* W4  = (const float*)d_in[14];
    const float* b4  = (const float*)d_in[15];
    const int*   ei  = (const int*)d_in[16];
    const int* src = ei;
    const int* tgt = ei + N_EDGES;
    float* out = (float*)d_out;

    edge_pass1<<<(N_EDGES / 8 + 255) / 256, 256>>>(src, tgt, ew, x);
    node_kernel<<<(N_NODES + 255) / 256, 256>>>(x, Wr1, br1, Ws1, Wr2, br2, Ws2);
    edge_pass2<<<(N_EDGES / 8 + 255) / 256, 256>>>(src, tgt, ew);

    // layer 1: 20000 -> 4000 ; 100 row-groups x 3 K-splits
    // KS=6668 (multiple of 4 — required for LDG.128 alignment on W); last split short.
    gemm40<<<300, 256>>>(W1, 0, 20000, 6668, 3, 4000);
    combine_kernel<<<(4000 * 8 + 255) / 256, 256>>>(b1, 3, 4000, 0);

    // layer 2: 4000 -> 800 ; 20 row-groups x 16 K-splits (KS=252, mult of 4; last short)
    gemm40<<<320, 256>>>(W2, 1, 4000, 252, 16, 800);
    combine_kernel<<<(800 * 8 + 255) / 256, 256>>>(b2, 16, 800, 1);

    // layer 3: 800 -> 160
    gemm8v<<<20, 256>>>(W3, b3, 800, 1);
    final_kernel<<<1, 256>>>(W4, b4, out);
}

// round 14
// speedup vs baseline: 1.0574x; 1.0574x over previous
#include <cuda_runtime.h>

#define N_NODES 160000
#define NODES_PER_GRAPH 20000
#define NBATCH 8
#define N_EDGES 5120000
#define HID 16
#define TKILE 1024

// ---------------- device scratch (no allocation allowed) ----------------
__device__ float d_s1[N_NODES];            // layer-1 scalar aggregation (zero invariant)
__device__ float d_p[N_NODES];             // h . Wr2 per node
__device__ float d_gt[N_NODES];            // h2 transposed: [20000][8]
__device__ float d_part[16 * 4000 * 8];    // K-split partials
__device__ float d_y1[4000 * NBATCH];
__device__ float d_y2[800 * NBATCH];
__device__ float d_y3[160 * NBATCH];

// ---------------- graph kernels (R12 config: 4 edges/thread) ----------------

__global__ void edge_pass1(const int* __restrict__ src, const int* __restrict__ tgt,
                           const float* __restrict__ ew, const float* __restrict__ x) {
    int i = blockIdx.x * blockDim.x + threadIdx.x;
    int base = i * 4;
    if (base >= N_EDGES) return;
    int4   s = *(const int4*)(src + base);
    int4   t = *(const int4*)(tgt + base);
    float4 w = *(const float4*)(ew + base);
    atomicAdd(&d_s1[t.x], w.x * __ldg(&x[s.x]));
    atomicAdd(&d_s1[t.y], w.y * __ldg(&x[s.y]));
    atomicAdd(&d_s1[t.z], w.z * __ldg(&x[s.z]));
    atomicAdd(&d_s1[t.w], w.w * __ldg(&x[s.w]));
}

__global__ void node_kernel(const float* __restrict__ x,
                            const float* __restrict__ Wr1, const float* __restrict__ br1,
                            const float* __restrict__ Ws1, const float* __restrict__ Wr2,
                            const float* __restrict__ br2, const float* __restrict__ Ws2) {
    int n = blockIdx.x * blockDim.x + threadIdx.x;
    if (n >= N_NODES) return;
    float s  = d_s1[n];
    d_s1[n] = 0.f;   // keep "s1 == 0 at entry" invariant across graph replays
    float xv = x[n];
    float pa = 0.f, qa = 0.f;
#pragma unroll
    for (int f = 0; f < HID; f++) {
        float h = fmaf(s, __ldg(&Wr1[f]), fmaf(xv, __ldg(&Ws1[f]), __ldg(&br1[f])));
        h = fmaxf(h, 0.f);
        pa = fmaf(__ldg(&Wr2[f]), h, pa);
        qa = fmaf(__ldg(&Ws2[f]), h, qa);
    }
    d_p[n] = pa;
    unsigned nu = (unsigned)n;
    unsigned b  = nu / NODES_PER_GRAPH;
    unsigned k  = nu - b * NODES_PER_GRAPH;
    d_gt[k * NBATCH + b] = qa + __ldg(&br2[0]);
}

__global__ void edge_pass2(const int* __restrict__ src, const int* __restrict__ tgt,
                           const float* __restrict__ ew) {
    int i = blockIdx.x * blockDim.x + threadIdx.x;
    int base = i * 4;
    if (base >= N_EDGES) return;
    int4   s = *(const int4*)(src + base);
    int4   t = *(const int4*)(tgt + base);
    float4 w = *(const float4*)(ew + base);
#define EP2_ONE(SS, TT, WW)                                            \
    {                                                                  \
        unsigned tu = (unsigned)(TT);                                  \
        unsigned b  = tu / NODES_PER_GRAPH;                            \
        unsigned k  = tu - b * NODES_PER_GRAPH;                        \
        atomicAdd(&d_gt[k * NBATCH + b], (WW) * __ldg(&d_p[SS]));      \
    }
    EP2_ONE(s.x, t.x, w.x);
    EP2_ONE(s.y, t.y, w.y);
    EP2_ONE(s.z, t.z, w.z);
    EP2_ONE(s.w, t.w, w.w);
#undef EP2_ONE
}

// ---------------- packed f32x2 helpers ----------------
__device__ __forceinline__ unsigned long long pack2(float v) {
    unsigned long long r;
    unsigned u = __float_as_uint(v);
    asm("mov.b64 %0, {%1, %1};" : "=l"(r) : "r"(u));
    return r;
}
__device__ __forceinline__ unsigned long long fma2(unsigned long long a,
                                                   unsigned long long b,
                                                   unsigned long long c) {
    unsigned long long d;
    asm("fma.rn.f32x2 %0, %1, %2, %3;" : "=l"(d) : "l"(a), "l"(b), "l"(c));
    return d;
}
__device__ __forceinline__ unsigned long long add2(unsigned long long a,
                                                   unsigned long long b) {
    unsigned long long d;
    asm("add.rn.f32x2 %0, %1, %2;" : "=l"(d) : "l"(a), "l"(b));
    return d;
}

// ---- gemm40: 40 rows/block (8 warps x 5 rows), K-split, packed f32x2,
//      LDG.128 W loads + swizzled-smem LDS.128 g loads.
//      CONTINUOUS cross-tile W prefetch: W chunk addresses are contiguous in k
//      across smem tiles, so the prefetch pipeline never drains at tile
//      boundaries — next tile's W is in flight during __syncthreads + staging.
// REQUIREMENT: KS % 4 == 0 (k0 must be 16B-aligned for LDG.128 on W).
// part[ks*J*8 + j*8 + b] = sum_{k in split ks} W[j,k] * gin_t[k][b]
#define ROWS_W 5
#define NCHUNK (TKILE / 128)
__global__ void __launch_bounds__(256, 2)
gemm40(const float* __restrict__ W, int gin_sel, int Ktot, int KS, int nsplit, int J) {
    const float* __restrict__ gin = (gin_sel == 0) ? d_gt : d_y1;

    __shared__ uint4 gs4[NCHUNK * 8 * 32];   // 32 KB: [chunk][pq][lane]

    int tid  = threadIdx.x;
    int lane = tid & 31;
    int wid  = tid >> 5;
    int rg   = blockIdx.x / nsplit;
    int ks   = blockIdx.x - rg * nsplit;
    int j0   = rg * (8 * ROWS_W);
    int row0 = j0 + wid * ROWS_W;
    int k0   = ks * KS;
    int kend = min(k0 + KS, Ktot);
    int kspan = kend - k0;

    // split-base W pointers (contiguous k across all tiles of this split)
    const float* Wb[ROWS_W];
#pragma unroll
    for (int r = 0; r < ROWS_W; r++) Wb[r] = W + (size_t)(row0 + r) * Ktot + k0;

    int nch_total = kspan >> 7;   // total full 128-k chunks in split

    unsigned long long acc[ROWS_W][4];
#pragma unroll
    for (int r = 0; r < ROWS_W; r++)
#pragma unroll
        for (int p = 0; p < 4; p++) acc[r][p] = 0ull;

    // prefetch global chunk 0 (W only — independent of staging)
    float4 wc[ROWS_W];
    if (nch_total > 0) {
#pragma unroll
        for (int r = 0; r < ROWS_W; r++)
            wc[r] = __ldg((const float4*)(Wb[r] + 4 * lane));
    }

    int c = 0;  // global chunk counter
    for (int kt = k0; kt < kend; kt += TKILE) {
        int kv = min(TKILE, kend - kt);
        __syncthreads();
        // stage g tile into swizzled layout, zero-pad beyond kv
        {
            unsigned long long* gs8 = (unsigned long long*)gs4;  // 8B units
            for (int k = tid; k < TKILE; k += 256) {
                float4 a, b;
                if (k < kv) {
                    a = __ldg((const float4*)(gin + (size_t)(kt + k) * 8));
                    b = __ldg((const float4*)(gin + (size_t)(kt + k) * 8 + 4));
                } else {
                    a = make_float4(0.f, 0.f, 0.f, 0.f);
                    b = a;
                }
                int cc = k >> 7;
                int kk = k & 127;
                int L  = kk >> 2;
                int q  = (kk >> 1) & 1;
                int rr = kk & 1;
                int base8 = ((cc << 3) + q) * 64 + L * 2 + rr;
                float2 p0 = make_float2(a.x, a.y);
                float2 p1 = make_float2(a.z, a.w);
                float2 p2 = make_float2(b.x, b.y);
                float2 p3 = make_float2(b.z, b.w);
                gs8[base8 + 0 * 128] = *(unsigned long long*)&p0;
                gs8[base8 + 1 * 128] = *(unsigned long long*)&p1;
                gs8[base8 + 2 * 128] = *(unsigned long long*)&p2;
                gs8[base8 + 3 * 128] = *(unsigned long long*)&p3;
            }
        }
        __syncthreads();

        int iters = kv >> 7;          // full chunks in this tile
        int rem   = kv - (iters << 7);

        for (int it = 0; it < iters; it++, c++) {
            // prefetch next GLOBAL chunk's W (crosses tile boundary)
            float4 wn[ROWS_W];
            bool have_next = (c + 1 < nch_total);
            int knext = ((c + 1) << 7) + 4 * lane;
#pragma unroll
            for (int r = 0; r < ROWS_W; r++)
                wn[r] = have_next ? __ldg((const float4*)(Wb[r] + knext))
                                  : make_float4(0.f, 0.f, 0.f, 0.f);

            const uint4* gsc = gs4 + (it << 8);  // this chunk: 8*32 entries

            // q = 0: k-pair (4L, 4L+1)
            {
                uint4 v[4];
#pragma unroll
                for (int p = 0; p < 4; p++)
                    v[p] = gsc[(p * 2 + 0) * 32 + lane];
#pragma unroll
                for (int r = 0; r < ROWS_W; r++) {
                    unsigned long long w0 = pack2(wc[r].x);
                    unsigned long long w1 = pack2(wc[r].y);
#pragma unroll
                    for (int p = 0; p < 4; p++) {
                        unsigned long long g0 = *(unsigned long long*)&v[p].x;
                        unsigned long long g1 = *(unsigned long long*)&v[p].z;
                        acc[r][p] = fma2(w0, g0, acc[r][p]);
                        acc[r][p] = fma2(w1, g1, acc[r][p]);
                    }
                }
            }
            // q = 1: k-pair (4L+2, 4L+3)
            {
                uint4 v[4];
#pragma unroll
                for (int p = 0; p < 4; p++)
                    v[p] = gsc[(p * 2 + 1) * 32 + lane];
#pragma unroll
                for (int r = 0; r < ROWS_W; r++) {
                    unsigned long long w2 = pack2(wc[r].z);
                    unsigned long long w3 = pack2(wc[r].w);
#pragma unroll
                    for (int p = 0; p < 4; p++) {
                        unsigned long long g0 = *(unsigned long long*)&v[p].x;
                        unsigned long long g1 = *(unsigned long long*)&v[p].z;
                        acc[r][p] = fma2(w2, g0, acc[r][p]);
                        acc[r][p] = fma2(w3, g1, acc[r][p]);
                    }
                }
            }
#pragma unroll
            for (int r = 0; r < ROWS_W; r++) wc[r] = wn[r];
        }

        // epilogue: ragged remainder (last tile only; guarded scalar loads)
        if (rem > 0) {
            unsigned long long* gs8 = (unsigned long long*)gs4;
            int kb = iters << 7;                       // local k base in tile
            int gb = kt - k0 + kb;                     // global k base in split
#pragma unroll
            for (int j = 0; j < 4; j++) {
                int kk = kb + 32 * j + lane;           // local
                if (kk < kv) {
                    float wv[ROWS_W];
#pragma unroll
                    for (int r = 0; r < ROWS_W; r++)
                        wv[r] = __ldg(Wb[r] + gb + 32 * j + lane);
                    int cc = kk >> 7;
                    int kl = kk & 127;
                    int L  = kl >> 2;
                    int q  = (kl >> 1) & 1;
                    int rr = kl & 1;
                    int base8 = ((cc << 3) + q) * 64 + L * 2 + rr;
#pragma unroll
                    for (int r = 0; r < ROWS_W; r++) {
                        unsigned long long wp = pack2(wv[r]);
#pragma unroll
                        for (int p = 0; p < 4; p++)
                            acc[r][p] = fma2(wp, gs8[base8 + p * 128], acc[r][p]);
                    }
                }
            }
        }
    }

    // cross-lane reduction; lanes 0..19 own one (row, b-pair) and store as u64
    unsigned long long keep = 0ull;
#pragma unroll
    for (int r = 0; r < ROWS_W; r++)
#pragma unroll
        for (int p = 0; p < 4; p++) {
            unsigned long long v = acc[r][p];
#pragma unroll
            for (int o = 16; o > 0; o >>= 1)
                v = add2(v, __shfl_xor_sync(0xffffffffu, v, o));
            if (lane == r * 4 + p) keep = v;
        }
    if (lane < ROWS_W * 4) {
        int r = lane >> 2;
        int p = lane & 3;
        *(unsigned long long*)&d_part[((size_t)ks * J + (row0 + r)) * 8 + 2 * p] = keep;
    }
}

// combine K-split partials: out[j][b] = relu(sum_s part[s][j][b] + bias[j])
__global__ void combine_kernel(const float* __restrict__ bias, int nsplit, int J,
                               int out_sel) {
    float* __restrict__ gout = (out_sel == 0) ? d_y1 : d_y2;
    int i = blockIdx.x * blockDim.x + threadIdx.x;
    if (i >= J * 8) return;
    int j = i >> 3;
    float v = __ldg(&bias[j]);
    for (int s = 0; s < nsplit; s++) v += d_part[(size_t)s * J * 8 + i];
    gout[i] = fmaxf(v, 0.f);
}

// batch-8 GEMV for layer 3 (160 x 800, tiny)
__global__ void gemm8v(const float* __restrict__ W, const float* __restrict__ bias,
                       int K, int do_relu) {
    const float* __restrict__ gin  = d_y2;
    float* __restrict__       gout = d_y3;

    __shared__ float red[64][8];
    int j0 = blockIdx.x * 8;
    int K4 = K >> 2;

    float acc[8][8];
#pragma unroll
    for (int j = 0; j < 8; j++)
#pragma unroll
        for (int b = 0; b < 8; b++) acc[j][b] = 0.f;

    const float4* gv = (const float4*)gin;
    for (int k4 = threadIdx.x; k4 < K4; k4 += 256) {
        float4 w[8];
#pragma unroll
        for (int j = 0; j < 8; j++)
            w[j] = __ldg((const float4*)(W + (size_t)(j0 + j) * K) + k4);
        float4 g[8];
#pragma unroll
        for (int i = 0; i < 8; i++) g[i] = __ldg(gv + (size_t)k4 * 8 + i);
#pragma unroll
        for (int j = 0; j < 8; j++) {
            float wj[4] = {w[j].x, w[j].y, w[j].z, w[j].w};
#pragma unroll
            for (int kk = 0; kk < 4; kk++) {
                float4 ga = g[kk * 2 + 0];
                float4 gb = g[kk * 2 + 1];
                acc[j][0] = fmaf(wj[kk], ga.x, acc[j][0]);
                acc[j][1] = fmaf(wj[kk], ga.y, acc[j][1]);
                acc[j][2] = fmaf(wj[kk], ga.z, acc[j][2]);
                acc[j][3] = fmaf(wj[kk], ga.w, acc[j][3]);
                acc[j][4] = fmaf(wj[kk], gb.x, acc[j][4]);
                acc[j][5] = fmaf(wj[kk], gb.y, acc[j][5]);
                acc[j][6] = fmaf(wj[kk], gb.z, acc[j][6]);
                acc[j][7] = fmaf(wj[kk], gb.w, acc[j][7]);
            }
        }
    }

    int lane = threadIdx.x & 31;
    int wid  = threadIdx.x >> 5;
#pragma unroll
    for (int j = 0; j < 8; j++) {
#pragma unroll
        for (int b = 0; b < 8; b++) {
            float v = acc[j][b];
#pragma unroll
            for (int o = 16; o > 0; o >>= 1)
                v += __shfl_down_sync(0xffffffffu, v, o);
            if (lane == 0) red[j * 8 + b][wid] = v;
        }
    }
    __syncthreads();
    if (threadIdx.x < 64) {
        int j = threadIdx.x >> 3;
        int b = threadIdx.x & 7;
        float v = 0.f;
#pragma unroll
        for (int w = 0; w < 8; w++) v += red[threadIdx.x][w];
        v += __ldg(&bias[j0 + j]);
        if (do_relu) v = fmaxf(v, 0.f);
        gout[(j0 + j) * 8 + b] = v;
    }
}

// final layer [8,160] @ W4^T [160,10] + b4, then log_softmax per row.
__global__ void final_kernel(const float* __restrict__ W4, const float* __restrict__ b4,
                             float* __restrict__ out) {
    int b    = threadIdx.x >> 5;
    int lane = threadIdx.x & 31;
    float z = -1e30f;
    if (lane < 10) {
        float acc = __ldg(&b4[lane]);
#pragma unroll 8
        for (int k = 0; k < 160; k++)
            acc = fmaf(__ldg(&W4[lane * 160 + k]), d_y3[k * 8 + b], acc);
        z = acc;
    }
    float m = z;
#pragma unroll
    for (int o = 16; o > 0; o >>= 1)
        m = fmaxf(m, __shfl_xor_sync(0xffffffffu, m, o));
    float e = (lane < 10) ? __expf(z - m) : 0.f;
    float ssum = e;
#pragma unroll
    for (int o = 16; o > 0; o >>= 1)
        ssum += __shfl_xor_sync(0xffffffffu, ssum, o);
    if (lane < 10) out[b * 10 + lane] = z - m - __logf(ssum);
}

// ---------------- launch ----------------
extern "C" void kernel_launch(void* const* d_in, const int* in_sizes, int n_in,
                              void* d_out, int out_size) {
    const float* x   = (const float*)d_in[0];
    const float* ew  = (const float*)d_in[1];
    const float* Wr1 = (const float*)d_in[2];
    const float* br1 = (const float*)d_in[3];
    const float* Ws1 = (const float*)d_in[4];
    const float* Wr2 = (const float*)d_in[5];
    const float* br2 = (const float*)d_in[6];
    const float* Ws2 = (const float*)d_in[7];
    const float* W1  = (const float*)d_in[8];
    const float* b1  = (const float*)d_in[9];
    const float* W2  = (const float*)d_in[10];
    const float* b2  = (const float*)d_in[11];
    const float* W3  = (const float*)d_in[12];
    const float* b3  = (const float*)d_in[13];
    const float* W4  = (const float*)d_in[14];
    const float* b4  = (const float*)d_in[15];
    const int*   ei  = (const int*)d_in[16];
    const int* src = ei;
    const int* tgt = ei + N_EDGES;
    float* out = (float*)d_out;

    edge_pass1<<<(N_EDGES / 4 + 255) / 256, 256>>>(src, tgt, ew, x);
    node_kernel<<<(N_NODES + 255) / 256, 256>>>(x, Wr1, br1, Ws1, Wr2, br2, Ws2);
    edge_pass2<<<(N_EDGES / 4 + 255) / 256, 256>>>(src, tgt, ew);

    // layer 1: 20000 -> 4000 ; 100 row-groups x 3 K-splits (KS=6668, mult of 4)
    gemm40<<<300, 256>>>(W1, 0, 20000, 6668, 3, 4000);
    combine_kernel<<<(4000 * 8 + 255) / 256, 256>>>(b1, 3, 4000, 0);

    // layer 2: 4000 -> 800 ; 20 row-groups x 8 K-splits (KS=500, mult of 4)
    gemm40<<<160, 256>>>(W2, 1, 4000, 500, 8, 800);
    combine_kernel<<<(800 * 8 + 255) / 256, 256>>>(b2, 8, 800, 1);

    // layer 3: 800 -> 160
    gemm8v<<<20, 256>>>(W3, b3, 800, 1);
    final_kernel<<<1, 256>>>(W4, b4, out);
}

// round 15
// speedup vs baseline: 1.0700x; 1.0119x over previous
#include <cuda_runtime.h>

#define N_NODES 160000
#define NODES_PER_GRAPH 20000
#define NBATCH 8
#define N_EDGES 5120000
#define HID 16
#define TK2 512
#define NCH2 (TK2 / 128)

// ---------------- device scratch (no allocation allowed) ----------------
__device__ float d_s1[N_NODES];            // layer-1 scalar aggregation (zero invariant)
__device__ float d_p[N_NODES];             // h . Wr2 per node
__device__ float d_gt[N_NODES];            // h2 transposed: [20000][8]
__device__ float d_part[16 * 4000 * 8];    // K-split partials
__device__ float d_y1[4000 * NBATCH];
__device__ float d_y2[800 * NBATCH];
__device__ float d_y3[160 * NBATCH];

// ---------------- graph kernels (4 edges/thread — proven config) ----------------

__global__ void edge_pass1(const int* __restrict__ src, const int* __restrict__ tgt,
                           const float* __restrict__ ew, const float* __restrict__ x) {
    int i = blockIdx.x * blockDim.x + threadIdx.x;
    int base = i * 4;
    if (base >= N_EDGES) return;
    int4   s = *(const int4*)(src + base);
    int4   t = *(const int4*)(tgt + base);
    float4 w = *(const float4*)(ew + base);
    atomicAdd(&d_s1[t.x], w.x * __ldg(&x[s.x]));
    atomicAdd(&d_s1[t.y], w.y * __ldg(&x[s.y]));
    atomicAdd(&d_s1[t.z], w.z * __ldg(&x[s.z]));
    atomicAdd(&d_s1[t.w], w.w * __ldg(&x[s.w]));
}

__global__ void node_kernel(const float* __restrict__ x,
                            const float* __restrict__ Wr1, const float* __restrict__ br1,
                            const float* __restrict__ Ws1, const float* __restrict__ Wr2,
                            const float* __restrict__ br2, const float* __restrict__ Ws2) {
    int n = blockIdx.x * blockDim.x + threadIdx.x;
    if (n >= N_NODES) return;
    float s  = d_s1[n];
    d_s1[n] = 0.f;   // keep "s1 == 0 at entry" invariant across graph replays
    float xv = x[n];
    float pa = 0.f, qa = 0.f;
#pragma unroll
    for (int f = 0; f < HID; f++) {
        float h = fmaf(s, __ldg(&Wr1[f]), fmaf(xv, __ldg(&Ws1[f]), __ldg(&br1[f])));
        h = fmaxf(h, 0.f);
        pa = fmaf(__ldg(&Wr2[f]), h, pa);
        qa = fmaf(__ldg(&Ws2[f]), h, qa);
    }
    d_p[n] = pa;
    unsigned nu = (unsigned)n;
    unsigned b  = nu / NODES_PER_GRAPH;
    unsigned k  = nu - b * NODES_PER_GRAPH;
    d_gt[k * NBATCH + b] = qa + __ldg(&br2[0]);
}

__global__ void edge_pass2(const int* __restrict__ src, const int* __restrict__ tgt,
                           const float* __restrict__ ew) {
    int i = blockIdx.x * blockDim.x + threadIdx.x;
    int base = i * 4;
    if (base >= N_EDGES) return;
    int4   s = *(const int4*)(src + base);
    int4   t = *(const int4*)(tgt + base);
    float4 w = *(const float4*)(ew + base);
#define EP2_ONE(SS, TT, WW)                                            \
    {                                                                  \
        unsigned tu = (unsigned)(TT);                                  \
        unsigned b  = tu / NODES_PER_GRAPH;                            \
        unsigned k  = tu - b * NODES_PER_GRAPH;                        \
        atomicAdd(&d_gt[k * NBATCH + b], (WW) * __ldg(&d_p[SS]));      \
    }
    EP2_ONE(s.x, t.x, w.x);
    EP2_ONE(s.y, t.y, w.y);
    EP2_ONE(s.z, t.z, w.z);
    EP2_ONE(s.w, t.w, w.w);
#undef EP2_ONE
}

// ---------------- packed f32x2 helpers ----------------
__device__ __forceinline__ unsigned long long pack2(float v) {
    unsigned long long r;
    unsigned u = __float_as_uint(v);
    asm("mov.b64 %0, {%1, %1};" : "=l"(r) : "r"(u));
    return r;
}
__device__ __forceinline__ unsigned long long fma2(unsigned long long a,
                                                   unsigned long long b,
                                                   unsigned long long c) {
    unsigned long long d;
    asm("fma.rn.f32x2 %0, %1, %2, %3;" : "=l"(d) : "l"(a), "l"(b), "l"(c));
    return d;
}
__device__ __forceinline__ unsigned long long add2(unsigned long long a,
                                                   unsigned long long b) {
    unsigned long long d;
    asm("add.rn.f32x2 %0, %1, %2;" : "=l"(d) : "l"(a), "l"(b));
    return d;
}

// ---- gemm40: 40 rows/block (8 warps x 5 rows), K-split, packed f32x2,
//      LDG.128 W loads + swizzled-smem LDS.128 g loads.
//      DOUBLE-BUFFERED g tiles (512 k each): staging for tile t+1 is issued
//      into the alternate buffer before computing tile t, hiding g-load
//      latency behind compute. Continuous cross-tile W prefetch retained.
// REQUIREMENT: KS % 4 == 0 (k0 must be 16B-aligned for LDG.128 on W).
// part[ks*J*8 + j*8 + b] = sum_{k in split ks} W[j,k] * gin_t[k][b]
#define ROWS_W 5
__global__ void __launch_bounds__(256, 2)
gemm40(const float* __restrict__ W, int gin_sel, int Ktot, int KS, int nsplit, int J) {
    const float* __restrict__ gin = (gin_sel == 0) ? d_gt : d_y1;

    __shared__ uint4 gs4[2][NCH2 * 8 * 32];   // 2 x 16 KB: [buf][chunk][pq][lane]

    int tid  = threadIdx.x;
    int lane = tid & 31;
    int wid  = tid >> 5;
    int rg   = blockIdx.x / nsplit;
    int ks   = blockIdx.x - rg * nsplit;
    int j0   = rg * (8 * ROWS_W);
    int row0 = j0 + wid * ROWS_W;
    int k0   = ks * KS;
    int kend = min(k0 + KS, Ktot);
    int kspan = kend - k0;
    int ntile = (kspan + TK2 - 1) / TK2;

    // split-base W pointers (contiguous k across all tiles of this split)
    const float* Wb[ROWS_W];
#pragma unroll
    for (int r = 0; r < ROWS_W; r++) Wb[r] = W + (size_t)(row0 + r) * Ktot + k0;

    int nch_total = kspan >> 7;   // total full 128-k chunks in split

    unsigned long long acc[ROWS_W][4];
#pragma unroll
    for (int r = 0; r < ROWS_W; r++)
#pragma unroll
        for (int p = 0; p < 4; p++) acc[r][p] = 0ull;

    // ---- staging lambda-equivalent (macro for NCU source attribution) ----
#define STAGE_TILE(TILE_IDX, BUF)                                               \
    {                                                                           \
        int kt_ = k0 + (TILE_IDX) * TK2;                                        \
        int kv_ = min(TK2, kend - kt_);                                         \
        unsigned long long* gs8 = (unsigned long long*)gs4[BUF];                \
        for (int k = tid; k < TK2; k += 256) {                                  \
            float4 a, b;                                                        \
            if (k < kv_) {                                                      \
                a = __ldg((const float4*)(gin + (size_t)(kt_ + k) * 8));        \
                b = __ldg((const float4*)(gin + (size_t)(kt_ + k) * 8 + 4));    \
            } else {                                                            \
                a = make_float4(0.f, 0.f, 0.f, 0.f);                            \
                b = a;                                                          \
            }                                                                   \
            int cc = k >> 7;                                                    \
            int kk = k & 127;                                                   \
            int L  = kk >> 2;                                                   \
            int q  = (kk >> 1) & 1;                                             \
            int rr = kk & 1;                                                    \
            int base8 = ((cc << 3) + q) * 64 + L * 2 + rr;                      \
            float2 p0 = make_float2(a.x, a.y);                                  \
            float2 p1 = make_float2(a.z, a.w);                                  \
            float2 p2 = make_float2(b.x, b.y);                                  \
            float2 p3 = make_float2(b.z, b.w);                                  \
            gs8[base8 + 0 * 128] = *(unsigned long long*)&p0;                   \
            gs8[base8 + 1 * 128] = *(unsigned long long*)&p1;                   \
            gs8[base8 + 2 * 128] = *(unsigned long long*)&p2;                   \
            gs8[base8 + 3 * 128] = *(unsigned long long*)&p3;                   \
        }                                                                       \
    }

    // prologue: stage tile 0, prefetch W chunk 0
    STAGE_TILE(0, 0);
    float4 wc[ROWS_W];
    if (nch_total > 0) {
#pragma unroll
        for (int r = 0; r < ROWS_W; r++)
            wc[r] = __ldg((const float4*)(Wb[r] + 4 * lane));
    }
    __syncthreads();

    int c = 0;  // global chunk counter
    for (int t = 0; t < ntile; t++) {
        int buf = t & 1;
        int kt  = k0 + t * TK2;
        int kv  = min(TK2, kend - kt);

        // stage NEXT tile into alternate buffer (overlaps with compute below)
        if (t + 1 < ntile) STAGE_TILE(t + 1, buf ^ 1);

        int iters = kv >> 7;          // full chunks in this tile
        int rem   = kv - (iters << 7);

        for (int it = 0; it < iters; it++, c++) {
            // prefetch next GLOBAL chunk's W (crosses tile boundary)
            float4 wn[ROWS_W];
            bool have_next = (c + 1 < nch_total);
            int knext = ((c + 1) << 7) + 4 * lane;
#pragma unroll
            for (int r = 0; r < ROWS_W; r++)
                wn[r] = have_next ? __ldg((const float4*)(Wb[r] + knext))
                                  : make_float4(0.f, 0.f, 0.f, 0.f);

            const uint4* gsc = gs4[buf] + (it << 8);  // this chunk: 8*32 entries

            // q = 0: k-pair (4L, 4L+1)
            {
                uint4 v[4];
#pragma unroll
                for (int p = 0; p < 4; p++)
                    v[p] = gsc[(p * 2 + 0) * 32 + lane];
#pragma unroll
                for (int r = 0; r < ROWS_W; r++) {
                    unsigned long long w0 = pack2(wc[r].x);
                    unsigned long long w1 = pack2(wc[r].y);
#pragma unroll
                    for (int p = 0; p < 4; p++) {
                        unsigned long long g0 = *(unsigned long long*)&v[p].x;
                        unsigned long long g1 = *(unsigned long long*)&v[p].z;
                        acc[r][p] = fma2(w0, g0, acc[r][p]);
                        acc[r][p] = fma2(w1, g1, acc[r][p]);
                    }
                }
            }
            // q = 1: k-pair (4L+2, 4L+3)
            {
                uint4 v[4];
#pragma unroll
                for (int p = 0; p < 4; p++)
                    v[p] = gsc[(p * 2 + 1) * 32 + lane];
#pragma unroll
                for (int r = 0; r < ROWS_W; r++) {
                    unsigned long long w2 = pack2(wc[r].z);
                    unsigned long long w3 = pack2(wc[r].w);
#pragma unroll
                    for (int p = 0; p < 4; p++) {
                        unsigned long long g0 = *(unsigned long long*)&v[p].x;
                        unsigned long long g1 = *(unsigned long long*)&v[p].z;
                        acc[r][p] = fma2(w2, g0, acc[r][p]);
                        acc[r][p] = fma2(w3, g1, acc[r][p]);
                    }
                }
            }
#pragma unroll
            for (int r = 0; r < ROWS_W; r++) wc[r] = wn[r];
        }

        // epilogue: ragged remainder (last tile only; guarded scalar loads)
        if (rem > 0) {
            unsigned long long* gs8 = (unsigned long long*)gs4[buf];
            int kb = iters << 7;                       // local k base in tile
            int gb = kt - k0 + kb;                     // global k base in split
#pragma unroll
            for (int j = 0; j < 4; j++) {
                int kk = kb + 32 * j + lane;           // local
                if (kk < kv) {
                    float wv[ROWS_W];
#pragma unroll
                    for (int r = 0; r < ROWS_W; r++)
                        wv[r] = __ldg(Wb[r] + gb + 32 * j + lane);
                    int cc = kk >> 7;
                    int kl = kk & 127;
                    int L  = kl >> 2;
                    int q  = (kl >> 1) & 1;
                    int rr = kl & 1;
                    int base8 = ((cc << 3) + q) * 64 + L * 2 + rr;
#pragma unroll
                    for (int r = 0; r < ROWS_W; r++) {
                        unsigned long long wp = pack2(wv[r]);
#pragma unroll
                        for (int p = 0; p < 4; p++)
                            acc[r][p] = fma2(wp, gs8[base8 + p * 128], acc[r][p]);
                    }
                }
            }
        }
        __syncthreads();
    }
#undef STAGE_TILE

    // cross-lane reduction; lanes 0..19 own one (row, b-pair) and store as u64
    unsigned long long keep = 0ull;
#pragma unroll
    for (int r = 0; r < ROWS_W; r++)
#pragma unroll
        for (int p = 0; p < 4; p++) {
            unsigned long long v = acc[r][p];
#pragma unroll
            for (int o = 16; o > 0; o >>= 1)
                v = add2(v, __shfl_xor_sync(0xffffffffu, v, o));
            if (lane == r * 4 + p) keep = v;
        }
    if (lane < ROWS_W * 4) {
        int r = lane >> 2;
        int p = lane & 3;
        *(unsigned long long*)&d_part[((size_t)ks * J + (row0 + r)) * 8 + 2 * p] = keep;
    }
}

// combine K-split partials: out[j][b] = relu(sum_s part[s][j][b] + bias[j])
__global__ void combine_kernel(const float* __restrict__ bias, int nsplit, int J,
                               int out_sel) {
    float* __restrict__ gout = (out_sel == 0) ? d_y1 : d_y2;
    int i = blockIdx.x * blockDim.x + threadIdx.x;
    if (i >= J * 8) return;
    int j = i >> 3;
    float v = __ldg(&bias[j]);
    for (int s = 0; s < nsplit; s++) v += d_part[(size_t)s * J * 8 + i];
    gout[i] = fmaxf(v, 0.f);
}

// batch-8 GEMV for layer 3 (160 x 800, tiny)
__global__ void gemm8v(const float* __restrict__ W, const float* __restrict__ bias,
                       int K, int do_relu) {
    const float* __restrict__ gin  = d_y2;
    float* __restrict__       gout = d_y3;

    __shared__ float red[64][8];
    int j0 = blockIdx.x * 8;
    int K4 = K >> 2;

    float acc[8][8];
#pragma unroll
    for (int j = 0; j < 8; j++)
#pragma unroll
        for (int b = 0; b < 8; b++) acc[j][b] = 0.f;

    const float4* gv = (const float4*)gin;
    for (int k4 = threadIdx.x; k4 < K4; k4 += 256) {
        float4 w[8];
#pragma unroll
        for (int j = 0; j < 8; j++)
            w[j] = __ldg((const float4*)(W + (size_t)(j0 + j) * K) + k4);
        float4 g[8];
#pragma unroll
        for (int i = 0; i < 8; i++) g[i] = __ldg(gv + (size_t)k4 * 8 + i);
#pragma unroll
        for (int j = 0; j < 8; j++) {
            float wj[4] = {w[j].x, w[j].y, w[j].z, w[j].w};
#pragma unroll
            for (int kk = 0; kk < 4; kk++) {
                float4 ga = g[kk * 2 + 0];
                float4 gb = g[kk * 2 + 1];
                acc[j][0] = fmaf(wj[kk], ga.x, acc[j][0]);
                acc[j][1] = fmaf(wj[kk], ga.y, acc[j][1]);
                acc[j][2] = fmaf(wj[kk], ga.z, acc[j][2]);
                acc[j][3] = fmaf(wj[kk], ga.w, acc[j][3]);
                acc[j][4] = fmaf(wj[kk], gb.x, acc[j][4]);
                acc[j][5] = fmaf(wj[kk], gb.y, acc[j][5]);
                acc[j][6] = fmaf(wj[kk], gb.z, acc[j][6]);
                acc[j][7] = fmaf(wj[kk], gb.w, acc[j][7]);
            }
        }
    }

    int lane = threadIdx.x & 31;
    int wid  = threadIdx.x >> 5;
#pragma unroll
    for (int j = 0; j < 8; j++) {
#pragma unroll
        for (int b = 0; b < 8; b++) {
            float v = acc[j][b];
#pragma unroll
            for (int o = 16; o > 0; o >>= 1)
                v += __shfl_down_sync(0xffffffffu, v, o);
            if (lane == 0) red[j * 8 + b][wid] = v;
        }
    }
    __syncthreads();
    if (threadIdx.x < 64) {
        int j = threadIdx.x >> 3;
        int b = threadIdx.x & 7;
        float v = 0.f;
#pragma unroll
        for (int w = 0; w < 8; w++) v += red[threadIdx.x][w];
        v += __ldg(&bias[j0 + j]);
        if (do_relu) v = fmaxf(v, 0.f);
        gout[(j0 + j) * 8 + b] = v;
    }
}

// final layer [8,160] @ W4^T [160,10] + b4, then log_softmax per row.
__global__ void final_kernel(const float* __restrict__ W4, const float* __restrict__ b4,
                             float* __restrict__ out) {
    int b    = threadIdx.x >> 5;
    int lane = threadIdx.x & 31;
    float z = -1e30f;
    if (lane < 10) {
        float acc = __ldg(&b4[lane]);
#pragma unroll 8
        for (int k = 0; k < 160; k++)
            acc = fmaf(__ldg(&W4[lane * 160 + k]), d_y3[k * 8 + b], acc);
        z = acc;
    }
    float m = z;
#pragma unroll
    for (int o = 16; o > 0; o >>= 1)
        m = fmaxf(m, __shfl_xor_sync(0xffffffffu, m, o));
    float e = (lane < 10) ? __expf(z - m) : 0.f;
    float ssum = e;
#pragma unroll
    for (int o = 16; o > 0; o >>= 1)
        ssum += __shfl_xor_sync(0xffffffffu, ssum, o);
    if (lane < 10) out[b * 10 + lane] = z - m - __logf(ssum);
}

// ---------------- launch ----------------
extern "C" void kernel_launch(void* const* d_in, const int* in_sizes, int n_in,
                              void* d_out, int out_size) {
    const float* x   = (const float*)d_in[0];
    const float* ew  = (const float*)d_in[1];
    const float* Wr1 = (const float*)d_in[2];
    const float* br1 = (const float*)d_in[3];
    const float* Ws1 = (const float*)d_in[4];
    const float* Wr2 = (const float*)d_in[5];
    const float* br2 = (const float*)d_in[6];
    const float* Ws2 = (const float*)d_in[7];
    const float* W1  = (const float*)d_in[8];
    const float* b1  = (const float*)d_in[9];
    const float* W2  = (const float*)d_in[10];
    const float* b2  = (const float*)d_in[11];
    const float* W3  = (const float*)d_in[12];
    const float* b3  = (const float*)d_in[13];
    const float* W4  = (const float*)d_in[14];
    const float* b4  = (const float*)d_in[15];
    const int*   ei  = (const int*)d_in[16];
    const int* src = ei;
    const int* tgt = ei + N_EDGES;
    float* out = (float*)d_out;

    edge_pass1<<<(N_EDGES / 4 + 255) / 256, 256>>>(src, tgt, ew, x);
    node_kernel<<<(N_NODES + 255) / 256, 256>>>(x, Wr1, br1, Ws1, Wr2, br2, Ws2);
    edge_pass2<<<(N_EDGES / 4 + 255) / 256, 256>>>(src, tgt, ew);

    // layer 1: 20000 -> 4000 ; 100 row-groups x 3 K-splits (KS=6668, mult of 4)
    gemm40<<<300, 256>>>(W1, 0, 20000, 6668, 3, 4000);
    combine_kernel<<<(4000 * 8 + 255) / 256, 256>>>(b1, 3, 4000, 0);

    // layer 2: 4000 -> 800 ; 20 row-groups x 16 K-splits (KS=256, no remainder)
    gemm40<<<320, 256>>>(W2, 1, 4000, 256, 16, 800);
    combine_kernel<<<(800 * 8 + 255) / 256, 256>>>(b2, 16, 800, 1);

    // layer 3: 800 -> 160
    gemm8v<<<20, 256>>>(W3, b3, 800, 1);
    final_kernel<<<1, 256>>>(W4, b4, out);
}

// round 16
// speedup vs baseline: 1.1043x; 1.0321x over previous
#include <cuda_runtime.h>
#include <cuda_fp16.h>

#define N_NODES 160000
#define NODES_PER_GRAPH 20000
#define NBATCH 8
#define N_EDGES 5120000
#define HID 16
#define TK2 512
#define NCH2 (TK2 / 128)

// ---------------- device scratch (no allocation allowed) ----------------
__device__ float  d_s1[N_NODES];           // layer-1 scalar aggregation (zero invariant)
__device__ __half d_xh[N_NODES];           // fp16 copy of x (gather-compressed)
__device__ __half d_ph[N_NODES];           // fp16 p = h . Wr2 per node (gather-compressed)
__device__ float  d_gt[N_NODES];           // h2 transposed: [20000][8]
__device__ float  d_part[16 * 4000 * 8];   // K-split partials
__device__ float  d_y1[4000 * NBATCH];
__device__ float  d_y2[800 * NBATCH];
__device__ float  d_y3[160 * NBATCH];

// ---------------- graph kernels ----------------

// convert x to fp16 gather table
__global__ void conv_x(const float* __restrict__ x) {
    int i = blockIdx.x * blockDim.x + threadIdx.x;
    if (i < N_NODES) d_xh[i] = __float2half(x[i]);
}

// pass 1: s1[tgt] += ew * xh[src]   (gather fp16, math fp32)
__global__ void edge_pass1(const int* __restrict__ src, const int* __restrict__ tgt,
                           const float* __restrict__ ew) {
    int i = blockIdx.x * blockDim.x + threadIdx.x;
    int base = i * 4;
    if (base >= N_EDGES) return;
    int4   s = *(const int4*)(src + base);
    int4   t = *(const int4*)(tgt + base);
    float4 w = *(const float4*)(ew + base);
    atomicAdd(&d_s1[t.x], w.x * __half2float(__ldg(&d_xh[s.x])));
    atomicAdd(&d_s1[t.y], w.y * __half2float(__ldg(&d_xh[s.y])));
    atomicAdd(&d_s1[t.z], w.z * __half2float(__ldg(&d_xh[s.z])));
    atomicAdd(&d_s1[t.w], w.w * __half2float(__ldg(&d_xh[s.w])));
}

// per node: compute p (fp16 gather table) and init gt with q + br2; re-zero s1.
// h itself is computed from the ORIGINAL fp32 x — only gathered values are fp16.
__global__ void node_kernel(const float* __restrict__ x,
                            const float* __restrict__ Wr1, const float* __restrict__ br1,
                            const float* __restrict__ Ws1, const float* __restrict__ Wr2,
                            const float* __restrict__ br2, const float* __restrict__ Ws2) {
    int n = blockIdx.x * blockDim.x + threadIdx.x;
    if (n >= N_NODES) return;
    float s  = d_s1[n];
    d_s1[n] = 0.f;   // keep "s1 == 0 at entry" invariant across graph replays
    float xv = x[n];
    float pa = 0.f, qa = 0.f;
#pragma unroll
    for (int f = 0; f < HID; f++) {
        float h = fmaf(s, __ldg(&Wr1[f]), fmaf(xv, __ldg(&Ws1[f]), __ldg(&br1[f])));
        h = fmaxf(h, 0.f);
        pa = fmaf(__ldg(&Wr2[f]), h, pa);
        qa = fmaf(__ldg(&Ws2[f]), h, qa);
    }
    d_ph[n] = __float2half(pa);
    unsigned nu = (unsigned)n;
    unsigned b  = nu / NODES_PER_GRAPH;
    unsigned k  = nu - b * NODES_PER_GRAPH;
    d_gt[k * NBATCH + b] = qa + __ldg(&br2[0]);
}

// pass 2: gt[transposed(tgt)] += ew * ph[src]   (gather fp16, math fp32)
__global__ void edge_pass2(const int* __restrict__ src, const int* __restrict__ tgt,
                           const float* __restrict__ ew) {
    int i = blockIdx.x * blockDim.x + threadIdx.x;
    int base = i * 4;
    if (base >= N_EDGES) return;
    int4   s = *(const int4*)(src + base);
    int4   t = *(const int4*)(tgt + base);
    float4 w = *(const float4*)(ew + base);
#define EP2_ONE(SS, TT, WW)                                                   \
    {                                                                         \
        unsigned tu = (unsigned)(TT);                                         \
        unsigned b  = tu / NODES_PER_GRAPH;                                   \
        unsigned k  = tu - b * NODES_PER_GRAPH;                               \
        atomicAdd(&d_gt[k * NBATCH + b],                                      \
                  (WW) * __half2float(__ldg(&d_ph[SS])));                     \
    }
    EP2_ONE(s.x, t.x, w.x);
    EP2_ONE(s.y, t.y, w.y);
    EP2_ONE(s.z, t.z, w.z);
    EP2_ONE(s.w, t.w, w.w);
#undef EP2_ONE
}

// ---------------- packed f32x2 helpers ----------------
__device__ __forceinline__ unsigned long long pack2(float v) {
    unsigned long long r;
    unsigned u = __float_as_uint(v);
    asm("mov.b64 %0, {%1, %1};" : "=l"(r) : "r"(u));
    return r;
}
__device__ __forceinline__ unsigned long long fma2(unsigned long long a,
                                                   unsigned long long b,
                                                   unsigned long long c) {
    unsigned long long d;
    asm("fma.rn.f32x2 %0, %1, %2, %3;" : "=l"(d) : "l"(a), "l"(b), "l"(c));
    return d;
}
__device__ __forceinline__ unsigned long long add2(unsigned long long a,
                                                   unsigned long long b) {
    unsigned long long d;
    asm("add.rn.f32x2 %0, %1, %2;" : "=l"(d) : "l"(a), "l"(b));
    return d;
}

// ---- gemm40: 40 rows/block (8 warps x 5 rows), K-split, packed f32x2,
//      LDG.128 W loads + swizzled-smem LDS.128 g loads, double-buffered g
//      tiles, continuous cross-tile W prefetch (proven R14/R15 config).
// REQUIREMENT: KS % 4 == 0 (k0 must be 16B-aligned for LDG.128 on W).
#define ROWS_W 5
__global__ void __launch_bounds__(256, 2)
gemm40(const float* __restrict__ W, int gin_sel, int Ktot, int KS, int nsplit, int J) {
    const float* __restrict__ gin = (gin_sel == 0) ? d_gt : d_y1;

    __shared__ uint4 gs4[2][NCH2 * 8 * 32];   // 2 x 16 KB: [buf][chunk][pq][lane]

    int tid  = threadIdx.x;
    int lane = tid & 31;
    int wid  = tid >> 5;
    int rg   = blockIdx.x / nsplit;
    int ks   = blockIdx.x - rg * nsplit;
    int j0   = rg * (8 * ROWS_W);
    int row0 = j0 + wid * ROWS_W;
    int k0   = ks * KS;
    int kend = min(k0 + KS, Ktot);
    int kspan = kend - k0;
    int ntile = (kspan + TK2 - 1) / TK2;

    const float* Wb[ROWS_W];
#pragma unroll
    for (int r = 0; r < ROWS_W; r++) Wb[r] = W + (size_t)(row0 + r) * Ktot + k0;

    int nch_total = kspan >> 7;

    unsigned long long acc[ROWS_W][4];
#pragma unroll
    for (int r = 0; r < ROWS_W; r++)
#pragma unroll
        for (int p = 0; p < 4; p++) acc[r][p] = 0ull;

#define STAGE_TILE(TILE_IDX, BUF)                                               \
    {                                                                           \
        int kt_ = k0 + (TILE_IDX) * TK2;                                        \
        int kv_ = min(TK2, kend - kt_);                                         \
        unsigned long long* gs8 = (unsigned long long*)gs4[BUF];                \
        for (int k = tid; k < TK2; k += 256) {                                  \
            float4 a, b;                                                        \
            if (k < kv_) {                                                      \
                a = __ldg((const float4*)(gin + (size_t)(kt_ + k) * 8));        \
                b = __ldg((const float4*)(gin + (size_t)(kt_ + k) * 8 + 4));    \
            } else {                                                            \
                a = make_float4(0.f, 0.f, 0.f, 0.f);                            \
                b = a;                                                          \
            }                                                                   \
            int cc = k >> 7;                                                    \
            int kk = k & 127;                                                   \
            int L  = kk >> 2;                                                   \
            int q  = (kk >> 1) & 1;                                             \
            int rr = kk & 1;                                                    \
            int base8 = ((cc << 3) + q) * 64 + L * 2 + rr;                      \
            float2 p0 = make_float2(a.x, a.y);                                  \
            float2 p1 = make_float2(a.z, a.w);                                  \
            float2 p2 = make_float2(b.x, b.y);                                  \
            float2 p3 = make_float2(b.z, b.w);                                  \
            gs8[base8 + 0 * 128] = *(unsigned long long*)&p0;                   \
            gs8[base8 + 1 * 128] = *(unsigned long long*)&p1;                   \
            gs8[base8 + 2 * 128] = *(unsigned long long*)&p2;                   \
            gs8[base8 + 3 * 128] = *(unsigned long long*)&p3;                   \
        }                                                                       \
    }

    STAGE_TILE(0, 0);
    float4 wc[ROWS_W];
    if (nch_total > 0) {
#pragma unroll
        for (int r = 0; r < ROWS_W; r++)
            wc[r] = __ldg((const float4*)(Wb[r] + 4 * lane));
    }
    __syncthreads();

    int c = 0;
    for (int t = 0; t < ntile; t++) {
        int buf = t & 1;
        int kt  = k0 + t * TK2;
        int kv  = min(TK2, kend - kt);

        if (t + 1 < ntile) STAGE_TILE(t + 1, buf ^ 1);

        int iters = kv >> 7;
        int rem   = kv - (iters << 7);

        for (int it = 0; it < iters; it++, c++) {
            float4 wn[ROWS_W];
            bool have_next = (c + 1 < nch_total);
            int knext = ((c + 1) << 7) + 4 * lane;
#pragma unroll
            for (int r = 0; r < ROWS_W; r++)
                wn[r] = have_next ? __ldg((const float4*)(Wb[r] + knext))
                                  : make_float4(0.f, 0.f, 0.f, 0.f);

            const uint4* gsc = gs4[buf] + (it << 8);

            {
                uint4 v[4];
#pragma unroll
                for (int p = 0; p < 4; p++)
                    v[p] = gsc[(p * 2 + 0) * 32 + lane];
#pragma unroll
                for (int r = 0; r < ROWS_W; r++) {
                    unsigned long long w0 = pack2(wc[r].x);
                    unsigned long long w1 = pack2(wc[r].y);
#pragma unroll
                    for (int p = 0; p < 4; p++) {
                        unsigned long long g0 = *(unsigned long long*)&v[p].x;
                        unsigned long long g1 = *(unsigned long long*)&v[p].z;
                        acc[r][p] = fma2(w0, g0, acc[r][p]);
                        acc[r][p] = fma2(w1, g1, acc[r][p]);
                    }
                }
            }
            {
                uint4 v[4];
#pragma unroll
                for (int p = 0; p < 4; p++)
                    v[p] = gsc[(p * 2 + 1) * 32 + lane];
#pragma unroll
                for (int r = 0; r < ROWS_W; r++) {
                    unsigned long long w2 = pack2(wc[r].z);
                    unsigned long long w3 = pack2(wc[r].w);
#pragma unroll
                    for (int p = 0; p < 4; p++) {
                        unsigned long long g0 = *(unsigned long long*)&v[p].x;
                        unsigned long long g1 = *(unsigned long long*)&v[p].z;
                        acc[r][p] = fma2(w2, g0, acc[r][p]);
                        acc[r][p] = fma2(w3, g1, acc[r][p]);
                    }
                }
            }
#pragma unroll
            for (int r = 0; r < ROWS_W; r++) wc[r] = wn[r];
        }

        if (rem > 0) {
            unsigned long long* gs8 = (unsigned long long*)gs4[buf];
            int kb = iters << 7;
            int gb = kt - k0 + kb;
#pragma unroll
            for (int j = 0; j < 4; j++) {
                int kk = kb + 32 * j + lane;
                if (kk < kv) {
                    float wv[ROWS_W];
#pragma unroll
                    for (int r = 0; r < ROWS_W; r++)
                        wv[r] = __ldg(Wb[r] + gb + 32 * j + lane);
                    int cc = kk >> 7;
                    int kl = kk & 127;
                    int L  = kl >> 2;
                    int q  = (kl >> 1) & 1;
                    int rr = kl & 1;
                    int base8 = ((cc << 3) + q) * 64 + L * 2 + rr;
#pragma unroll
                    for (int r = 0; r < ROWS_W; r++) {
                        unsigned long long wp = pack2(wv[r]);
#pragma unroll
                        for (int p = 0; p < 4; p++)
                            acc[r][p] = fma2(wp, gs8[base8 + p * 128], acc[r][p]);
                    }
                }
            }
        }
        __syncthreads();
    }
#undef STAGE_TILE

    unsigned long long keep = 0ull;
#pragma unroll
    for (int r = 0; r < ROWS_W; r++)
#pragma unroll
        for (int p = 0; p < 4; p++) {
            unsigned long long v = acc[r][p];
#pragma unroll
            for (int o = 16; o > 0; o >>= 1)
                v = add2(v, __shfl_xor_sync(0xffffffffu, v, o));
            if (lane == r * 4 + p) keep = v;
        }
    if (lane < ROWS_W * 4) {
        int r = lane >> 2;
        int p = lane & 3;
        *(unsigned long long*)&d_part[((size_t)ks * J + (row0 + r)) * 8 + 2 * p] = keep;
    }
}

// combine K-split partials: out[j][b] = relu(sum_s part[s][j][b] + bias[j])
__global__ void combine_kernel(const float* __restrict__ bias, int nsplit, int J,
                               int out_sel) {
    float* __restrict__ gout = (out_sel == 0) ? d_y1 : d_y2;
    int i = blockIdx.x * blockDim.x + threadIdx.x;
    if (i >= J * 8) return;
    int j = i >> 3;
    float v = __ldg(&bias[j]);
    for (int s = 0; s < nsplit; s++) v += d_part[(size_t)s * J * 8 + i];
    gout[i] = fmaxf(v, 0.f);
}

// batch-8 GEMV for layer 3 (160 x 800, tiny)
__global__ void gemm8v(const float* __restrict__ W, const float* __restrict__ bias,
                       int K, int do_relu) {
    const float* __restrict__ gin  = d_y2;
    float* __restrict__       gout = d_y3;

    __shared__ float red[64][8];
    int j0 = blockIdx.x * 8;
    int K4 = K >> 2;

    float acc[8][8];
#pragma unroll
    for (int j = 0; j < 8; j++)
#pragma unroll
        for (int b = 0; b < 8; b++) acc[j][b] = 0.f;

    const float4* gv = (const float4*)gin;
    for (int k4 = threadIdx.x; k4 < K4; k4 += 256) {
        float4 w[8];
#pragma unroll
        for (int j = 0; j < 8; j++)
            w[j] = __ldg((const float4*)(W + (size_t)(j0 + j) * K) + k4);
        float4 g[8];
#pragma unroll
        for (int i = 0; i < 8; i++) g[i] = __ldg(gv + (size_t)k4 * 8 + i);
#pragma unroll
        for (int j = 0; j < 8; j++) {
            float wj[4] = {w[j].x, w[j].y, w[j].z, w[j].w};
#pragma unroll
            for (int kk = 0; kk < 4; kk++) {
                float4 ga = g[kk * 2 + 0];
                float4 gb = g[kk * 2 + 1];
                acc[j][0] = fmaf(wj[kk], ga.x, acc[j][0]);
                acc[j][1] = fmaf(wj[kk], ga.y, acc[j][1]);
                acc[j][2] = fmaf(wj[kk], ga.z, acc[j][2]);
                acc[j][3] = fmaf(wj[kk], ga.w, acc[j][3]);
                acc[j][4] = fmaf(wj[kk], gb.x, acc[j][4]);
                acc[j][5] = fmaf(wj[kk], gb.y, acc[j][5]);
                acc[j][6] = fmaf(wj[kk], gb.z, acc[j][6]);
                acc[j][7] = fmaf(wj[kk], gb.w, acc[j][7]);
            }
        }
    }

    int lane = threadIdx.x & 31;
    int wid  = threadIdx.x >> 5;
#pragma unroll
    for (int j = 0; j < 8; j++) {
#pragma unroll
        for (int b = 0; b < 8; b++) {
            float v = acc[j][b];
#pragma unroll
            for (int o = 16; o > 0; o >>= 1)
                v += __shfl_down_sync(0xffffffffu, v, o);
            if (lane == 0) red[j * 8 + b][wid] = v;
        }
    }
    __syncthreads();
    if (threadIdx.x < 64) {
        int j = threadIdx.x >> 3;
        int b = threadIdx.x & 7;
        float v = 0.f;
#pragma unroll
        for (int w = 0; w < 8; w++) v += red[threadIdx.x][w];
        v += __ldg(&bias[j0 + j]);
        if (do_relu) v = fmaxf(v, 0.f);
        gout[(j0 + j) * 8 + b] = v;
    }
}

// final layer [8,160] @ W4^T [160,10] + b4, then log_softmax per row.
__global__ void final_kernel(const float* __restrict__ W4, const float* __restrict__ b4,
                             float* __restrict__ out) {
    int b    = threadIdx.x >> 5;
    int lane = threadIdx.x & 31;
    float z = -1e30f;
    if (lane < 10) {
        float acc = __ldg(&b4[lane]);
#pragma unroll 8
        for (int k = 0; k < 160; k++)
            acc = fmaf(__ldg(&W4[lane * 160 + k]), d_y3[k * 8 + b], acc);
        z = acc;
    }
    float m = z;
#pragma unroll
    for (int o = 16; o > 0; o >>= 1)
        m = fmaxf(m, __shfl_xor_sync(0xffffffffu, m, o));
    float e = (lane < 10) ? __expf(z - m) : 0.f;
    float ssum = e;
#pragma unroll
    for (int o = 16; o > 0; o >>= 1)
        ssum += __shfl_xor_sync(0xffffffffu, ssum, o);
    if (lane < 10) out[b * 10 + lane] = z - m - __logf(ssum);
}

// ---------------- launch ----------------
extern "C" void kernel_launch(void* const* d_in, const int* in_sizes, int n_in,
                              void* d_out, int out_size) {
    const float* x   = (const float*)d_in[0];
    const float* ew  = (const float*)d_in[1];
    const float* Wr1 = (const float*)d_in[2];
    const float* br1 = (const float*)d_in[3];
    const float* Ws1 = (const float*)d_in[4];
    const float* Wr2 = (const float*)d_in[5];
    const float* br2 = (const float*)d_in[6];
    const float* Ws2 = (const float*)d_in[7];
    const float* W1  = (const float*)d_in[8];
    const float* b1  = (const float*)d_in[9];
    const float* W2  = (const float*)d_in[10];
    const float* b2  = (const float*)d_in[11];
    const float* W3  = (const float*)d_in[12];
    const float* b3  = (const float*)d_in[13];
    const float* W4  = (const float*)d_in[14];
    const float* b4  = (const float*)d_in[15];
    const int*   ei  = (const int*)d_in[16];
    const int* src = ei;
    const int* tgt = ei + N_EDGES;
    float* out = (float*)d_out;

    conv_x<<<(N_NODES + 255) / 256, 256>>>(x);
    edge_pass1<<<(N_EDGES / 4 + 255) / 256, 256>>>(src, tgt, ew);
    node_kernel<<<(N_NODES + 255) / 256, 256>>>(x, Wr1, br1, Ws1, Wr2, br2, Ws2);
    edge_pass2<<<(N_EDGES / 4 + 255) / 256, 256>>>(src, tgt, ew);

    // layer 1: 20000 -> 4000 ; 100 row-groups x 3 K-splits
    // KS=6784 = 53*128 (mult of 4; splits 0,1 have no ragged remainder)
    gemm40<<<300, 256>>>(W1, 0, 20000, 6784, 3, 4000);
    combine_kernel<<<(4000 * 8 + 255) / 256, 256>>>(b1, 3, 4000, 0);

    // layer 2: 4000 -> 800 ; 20 row-groups x 16 K-splits (KS=256, no remainder)
    gemm40<<<320, 256>>>(W2, 1, 4000, 256, 16, 800);
    combine_kernel<<<(800 * 8 + 255) / 256, 256>>>(b2, 16, 800, 1);

    // layer 3: 800 -> 160
    gemm8v<<<20, 256>>>(W3, b3, 800, 1);
    final_kernel<<<1, 256>>>(W4, b4, out);
}